// round 13
// baseline (speedup 1.0000x reference)
#include <cuda_runtime.h>
#include <cstdint>

#define BB   256
#define TT   512
#define II   64
#define HH   256
#define G4   1024   // 4*H
#define TPB  256

// ---------------- global scratch (static; no allocations) ------------------
__device__ float g_xg[(size_t)BB * TT * G4];   // [t][b][unit*4+gate]  512MB
__device__ float g_h1[(size_t)BB * TT * HH];   // [b][t][h]            128MB
__device__ float g_h[2][BB * HH];              // [b][h] double-buffered
__device__ float g_last[BB * HH];

// ---------------- helpers ---------------------------------------------------
__device__ __forceinline__ unsigned long long pack2(float x) {
    unsigned long long r;
    asm("mov.b64 %0, {%1, %1};" : "=l"(r) : "f"(x));
    return r;
}
__device__ __forceinline__ void fma2(unsigned long long& acc,
                                     unsigned long long a, unsigned long long b) {
    asm("fma.rn.f32x2 %0, %1, %2, %0;" : "+l"(acc) : "l"(a), "l"(b));
}
__device__ __forceinline__ float hadd2(unsigned long long v) {
    union { unsigned long long u; float2 f; } cv; cv.u = v;
    return cv.f.x + cv.f.y;
}
__device__ __forceinline__ float sigmoidf_(float x) {
    return 1.0f / (1.0f + __expf(-x));
}
__device__ __forceinline__ float tanhf_(float x) {
    return 1.0f - 2.0f / (__expf(2.0f * x) + 1.0f);
}

// ======================= bulk GEMM: xg = A @ W^T + bias =====================
// A[M=BB*TT][K] row-major (row m = b*T + t), W[G4][K] row-major with gate-block
// rows; output column ocol = unit*4 + gate, written to g_xg[t*BB + b][ocol].
template<int K, bool A_IS_H1>
__global__ void __launch_bounds__(256, 2)
gemm_xg_kernel(const float* __restrict__ Ain, const float* __restrict__ W,
               const float* __restrict__ bih, const float* __restrict__ bhh)
{
    __shared__ float As[16 * 132];
    __shared__ float Bs[16 * 132];
    const float* A = A_IS_H1 ? g_h1 : Ain;

    const int m0  = (int)(blockIdx.x >> 3) * 128;
    const int n0  = (int)(blockIdx.x & 7) * 128;
    const int tid = threadIdx.x;
    const int tx  = tid & 15;
    const int ty  = tid >> 4;
    const int lm  = tid >> 2;
    const int lk  = (tid & 3) * 4;

    unsigned long long acc[8][4];
    #pragma unroll
    for (int m = 0; m < 8; m++)
        #pragma unroll
        for (int n = 0; n < 4; n++) acc[m][n] = 0ull;

    for (int k0 = 0; k0 < K; k0 += 16) {
        #pragma unroll
        for (int i = 0; i < 2; i++) {
            int m = lm + i * 64;
            int ocol = n0 + m;
            int grow = (ocol & 3) * HH + (ocol >> 2);     // gate-interleave
            float4 va = *(const float4*)(A + (size_t)(m0 + m) * K + k0 + lk);
            float4 vb = *(const float4*)(W + (size_t)grow * K + k0 + lk);
            As[(lk + 0) * 132 + m] = va.x;  As[(lk + 1) * 132 + m] = va.y;
            As[(lk + 2) * 132 + m] = va.z;  As[(lk + 3) * 132 + m] = va.w;
            Bs[(lk + 0) * 132 + m] = vb.x;  Bs[(lk + 1) * 132 + m] = vb.y;
            Bs[(lk + 2) * 132 + m] = vb.z;  Bs[(lk + 3) * 132 + m] = vb.w;
        }
        __syncthreads();
        #pragma unroll
        for (int k = 0; k < 16; k++) {
            const float* ar = As + k * 132 + ty * 8;
            const float* br = Bs + k * 132 + tx * 8;
            ulonglong2 b0 = *(const ulonglong2*)(br);
            ulonglong2 b1 = *(const ulonglong2*)(br + 4);
            float4 a0 = *(const float4*)(ar);
            float4 a1 = *(const float4*)(ar + 4);
            float am[8] = {a0.x, a0.y, a0.z, a0.w, a1.x, a1.y, a1.z, a1.w};
            #pragma unroll
            for (int m = 0; m < 8; m++) {
                unsigned long long wd = pack2(am[m]);
                fma2(acc[m][0], wd, b0.x);
                fma2(acc[m][1], wd, b0.y);
                fma2(acc[m][2], wd, b1.x);
                fma2(acc[m][3], wd, b1.y);
            }
        }
        __syncthreads();
    }

    const int col = n0 + tx * 8;
    float bias[8];
    #pragma unroll
    for (int j = 0; j < 8; j++) {
        int oc = col + j;
        int grow = (oc & 3) * HH + (oc >> 2);
        bias[j] = bih[grow] + bhh[grow];
    }

    #pragma unroll
    for (int m = 0; m < 8; m++) {
        int mi   = m0 + ty * 8 + m;                  // = b*T + t
        int orow = (mi & (TT - 1)) * BB + (mi >> 9); // -> t*B + b
        float o[8];
        #pragma unroll
        for (int n = 0; n < 4; n++) {
            union { unsigned long long u; float2 f; } cv; cv.u = acc[m][n];
            o[2 * n]     = cv.f.x + bias[2 * n];
            o[2 * n + 1] = cv.f.y + bias[2 * n + 1];
        }
        float4* dst = (float4*)(g_xg + (size_t)orow * G4 + col);
        dst[0] = make_float4(o[0], o[1], o[2], o[3]);
        dst[1] = make_float4(o[4], o[5], o[6], o[7]);
    }
}

// ======================= cluster-synced recurrent layer =====================
// grid = 128 CTAs, clusters of 8: cluster = one batch tile (16 rows), the 8
// CTAs cover the 256 hidden units (32 each). Row r of the CTA's gate slice
// maps to (unit = r>>2, gate = r&3).
// SMEM (floats):
//   Ws_t  [128][260]  row-major rows, k-contiguous (k-pair packing for fp32x2)
//   Is_t  [16][260]   h_{t-1}, batch-row-major, k-contiguous
//   gts   [128][17]   gate pre-activations (Whh part)
//   h_s   [16][33]    h staging for coalesced writes
#define SM_WS  (128 * 260)
#define SM_IS  (16 * 260)
#define SM_GT  (128 * 17)
#define SM_HS  (16 * 33)
#define SMEM_FLOATS (SM_WS + SM_IS + SM_GT + SM_HS)
#define SMEM_BYTES  (SMEM_FLOATS * 4)

__device__ __forceinline__ void cluster_arrive_() {
    asm volatile("fence.acq_rel.cluster;" ::: "memory");
    asm volatile("barrier.cluster.arrive.aligned;" ::: "memory");
}
__device__ __forceinline__ void cluster_wait_() {
    asm volatile("barrier.cluster.wait.aligned;" ::: "memory");
}

__global__ void __launch_bounds__(TPB, 1) __cluster_dims__(8, 1, 1)
lstm_layer_kernel(const float* __restrict__ Whh, int layer)
{
    extern __shared__ float smem[];
    float* Ws_t = smem;
    float* Is_t = Ws_t + SM_WS;
    float* gts  = Is_t + SM_IS;
    float* h_s  = gts + SM_GT;

    const int tid  = threadIdx.x;
    const int bt   = blockIdx.x >> 3;   // 16 batch tiles of 16
    const int ht   = blockIdx.x & 7;    // 8 hidden tiles of 32 units
    const int b0   = bt * 16;
    const int hu0u = ht * 32;

    // GEMM mapping: warp tile 16 rows x 16 batch; thread 2 rows x 4 batch
    const int warp = tid >> 5;
    const int lane = tid & 31;
    const int r0   = warp * 16 + (lane & 7) * 2;
    const int bq0  = (lane >> 3) * 4;

    // activation mapping: elements e = tid, tid+256; uu = e>>4, bb = e&15
    const int a_bb = tid & 15;
    const int a_u0 = tid >> 4;          // 0..15 ; second element: +16

    // ---- load weight slice (rows gate-interleaved, k-contiguous) ----
    for (int i4 = tid; i4 < 128 * 64; i4 += TPB) {
        int r  = i4 >> 6;
        int kc = (i4 & 63) << 2;
        int grow = (r & 3) * HH + hu0u + (r >> 2);
        float4 v = *(const float4*)(Whh + (size_t)grow * HH + kc);
        *(float4*)(Ws_t + r * 260 + kc) = v;
    }
    // ---- zero our h slice in buffer 0 ----
    if (tid < 128) {
        int bb = tid >> 3, u4 = (tid & 7) * 4;
        *(float4*)(&g_h[0][(size_t)(b0 + bb) * HH + hu0u + u4]) =
            make_float4(0.f, 0.f, 0.f, 0.f);
    }
    __syncthreads();
    cluster_arrive_();

    float c0 = 0.0f, c1 = 0.0f;
    float4 xg0, xg1;
    // prefetch xg for t=0 (independent of h)
    xg0 = __ldcg((const float4*)(g_xg + (size_t)(0 * BB + b0 + a_bb) * G4
                                       + (hu0u + a_u0) * 4));
    xg1 = __ldcg((const float4*)(g_xg + (size_t)(0 * BB + b0 + a_bb) * G4
                                       + (hu0u + a_u0 + 16) * 4));
    cluster_wait_();

    for (int t = 0; t < TT; t++) {
        const int cur = t & 1;
        const int nxt = cur ^ 1;

        // ---- fill Is_t[bb][k] from g_h[cur] (coalesced LDG) ----
        {
            const int fbb = tid >> 4;          // 0..15 batch row
            const int fcj = tid & 15;          // chunk lane
            const float* src = g_h[cur] + (size_t)(b0 + fbb) * HH;
            float* dstrow = Is_t + fbb * 260;
            #pragma unroll
            for (int j = 0; j < 4; j++) {
                int c = fcj + 16 * j;          // float4 chunk 0..63
                float4 v = __ldcg((const float4*)(src + c * 4));
                *(float4*)(dstrow + c * 4) = v;
            }
        }
        __syncthreads();

        // ---- GEMM: gts[r][b] = sum_k Whh_r[k] * h[b][k]  (k-pair fp32x2) ----
        {
            unsigned long long acc[2][4];
            #pragma unroll
            for (int r = 0; r < 2; r++)
                #pragma unroll
                for (int j = 0; j < 4; j++) acc[r][j] = 0ull;

            const float* wp0 = Ws_t + r0 * 260;
            const float* wp1 = wp0 + 260;
            const float* ip  = Is_t + bq0 * 260;

            #pragma unroll 4
            for (int kc = 0; kc < HH; kc += 4) {
                ulonglong2 w0 = *(const ulonglong2*)(wp0 + kc);
                ulonglong2 w1 = *(const ulonglong2*)(wp1 + kc);
                ulonglong2 h0 = *(const ulonglong2*)(ip + 0 * 260 + kc);
                ulonglong2 h1 = *(const ulonglong2*)(ip + 1 * 260 + kc);
                ulonglong2 h2 = *(const ulonglong2*)(ip + 2 * 260 + kc);
                ulonglong2 h3 = *(const ulonglong2*)(ip + 3 * 260 + kc);
                fma2(acc[0][0], w0.x, h0.x);  fma2(acc[0][0], w0.y, h0.y);
                fma2(acc[0][1], w0.x, h1.x);  fma2(acc[0][1], w0.y, h1.y);
                fma2(acc[0][2], w0.x, h2.x);  fma2(acc[0][2], w0.y, h2.y);
                fma2(acc[0][3], w0.x, h3.x);  fma2(acc[0][3], w0.y, h3.y);
                fma2(acc[1][0], w1.x, h0.x);  fma2(acc[1][0], w1.y, h0.y);
                fma2(acc[1][1], w1.x, h1.x);  fma2(acc[1][1], w1.y, h1.y);
                fma2(acc[1][2], w1.x, h2.x);  fma2(acc[1][2], w1.y, h2.y);
                fma2(acc[1][3], w1.x, h3.x);  fma2(acc[1][3], w1.y, h3.y);
            }
            #pragma unroll
            for (int r = 0; r < 2; r++)
                #pragma unroll
                for (int j = 0; j < 4; j++)
                    gts[(r0 + r) * 17 + bq0 + j] = hadd2(acc[r][j]);
        }
        __syncthreads();

        // ---- activation: 2 elements per thread, c in registers ----
        {
            // element 0: (uu = a_u0, bb = a_bb)
            float gi = gts[(a_u0 * 4 + 0) * 17 + a_bb] + xg0.x;
            float gf = gts[(a_u0 * 4 + 1) * 17 + a_bb] + xg0.y;
            float gg = gts[(a_u0 * 4 + 2) * 17 + a_bb] + xg0.z;
            float go = gts[(a_u0 * 4 + 3) * 17 + a_bb] + xg0.w;
            c0 = sigmoidf_(gf) * c0 + sigmoidf_(gi) * tanhf_(gg);
            float h0v = sigmoidf_(go) * tanhf_(c0);
            h_s[a_bb * 33 + a_u0] = h0v;
            // element 1: (uu = a_u0+16, bb = a_bb)
            int u1 = a_u0 + 16;
            gi = gts[(u1 * 4 + 0) * 17 + a_bb] + xg1.x;
            gf = gts[(u1 * 4 + 1) * 17 + a_bb] + xg1.y;
            gg = gts[(u1 * 4 + 2) * 17 + a_bb] + xg1.z;
            go = gts[(u1 * 4 + 3) * 17 + a_bb] + xg1.w;
            c1 = sigmoidf_(gf) * c1 + sigmoidf_(gi) * tanhf_(gg);
            float h1v = sigmoidf_(go) * tanhf_(c1);
            h_s[a_bb * 33 + u1] = h1v;
        }
        __syncthreads();

        // ---- write h to g_h[nxt] (+ h1 / last), coalesced via h_s ----
        if (tid < 128) {
            int bb = tid >> 3, u4 = (tid & 7) * 4;
            float4 v = make_float4(h_s[bb * 33 + u4 + 0], h_s[bb * 33 + u4 + 1],
                                   h_s[bb * 33 + u4 + 2], h_s[bb * 33 + u4 + 3]);
            *(float4*)(&g_h[nxt][(size_t)(b0 + bb) * HH + hu0u + u4]) = v;
        } else {
            int t2 = tid - 128;
            int bb = t2 >> 3, u4 = (t2 & 7) * 4;
            float4 v = make_float4(h_s[bb * 33 + u4 + 0], h_s[bb * 33 + u4 + 1],
                                   h_s[bb * 33 + u4 + 2], h_s[bb * 33 + u4 + 3]);
            if (layer == 0) {
                *(float4*)(&g_h1[((size_t)(b0 + bb) * TT + t) * HH + hu0u + u4]) = v;
            } else if (t == TT - 1) {
                *(float4*)(&g_last[(size_t)(b0 + bb) * HH + hu0u + u4]) = v;
            }
        }

        cluster_arrive_();
        // prefetch xg for t+1 while the cluster drains
        if (t + 1 < TT) {
            xg0 = __ldcg((const float4*)(g_xg + (size_t)((t + 1) * BB + b0 + a_bb) * G4
                                               + (hu0u + a_u0) * 4));
            xg1 = __ldcg((const float4*)(g_xg + (size_t)((t + 1) * BB + b0 + a_bb) * G4
                                               + (hu0u + a_u0 + 16) * 4));
        }
        cluster_wait_();
    }
}

// ======================= epilogue ===========================================
__global__ void __launch_bounds__(256)
epilogue_kernel(const float* __restrict__ W1, const float* __restrict__ b1,
                const float* __restrict__ W2, const float* __restrict__ b2,
                float* __restrict__ out)
{
    const int b    = blockIdx.x;
    const int tid  = threadIdx.x;
    const int lane = tid & 31;
    const int warp = tid >> 5;

    __shared__ float last_s[HH];
    __shared__ float y_s[5 * HH];

    last_s[tid] = g_last[(size_t)b * HH + tid];
    __syncthreads();

    for (int j = warp; j < 5 * HH; j += 8) {
        const float* wr = W1 + (size_t)j * HH;
        float acc = 0.0f;
        for (int k = lane; k < HH; k += 32) acc += wr[k] * last_s[k];
        #pragma unroll
        for (int o = 16; o; o >>= 1) acc += __shfl_down_sync(0xffffffffu, acc, o);
        if (lane == 0) y_s[j] = acc + b1[j];
    }
    __syncthreads();

    if (warp < 4) {
        const float* wr = W2 + (size_t)warp * (5 * HH);
        float acc = 0.0f;
        for (int j = lane; j < 5 * HH; j += 32) acc += wr[j] * y_s[j];
        #pragma unroll
        for (int o = 16; o; o >>= 1) acc += __shfl_down_sync(0xffffffffu, acc, o);
        if (lane == 0) out[b * 4 + warp] = acc + b2[warp];
    }
}

// ======================= launcher ===========================================
extern "C" void kernel_launch(void* const* d_in, const int* in_sizes, int n_in,
                              void* d_out, int out_size)
{
    const float* x    = (const float*)d_in[0];
    const float* Wih0 = (const float*)d_in[1];
    const float* Whh0 = (const float*)d_in[2];
    const float* bih0 = (const float*)d_in[3];
    const float* bhh0 = (const float*)d_in[4];
    const float* Wih1 = (const float*)d_in[5];
    const float* Whh1 = (const float*)d_in[6];
    const float* bih1 = (const float*)d_in[7];
    const float* bhh1 = (const float*)d_in[8];
    const float* W1   = (const float*)d_in[9];
    const float* b1   = (const float*)d_in[10];
    const float* W2   = (const float*)d_in[11];
    const float* b2   = (const float*)d_in[12];
    float* out = (float*)d_out;

    static bool attr_set = false;
    if (!attr_set) {
        cudaFuncSetAttribute(lstm_layer_kernel,
                             cudaFuncAttributeMaxDynamicSharedMemorySize, SMEM_BYTES);
        attr_set = true;
    }

    const int gemm_grid = (BB * TT / 128) * 8;   // 8192

    gemm_xg_kernel<II, false><<<gemm_grid, 256>>>(x, Wih0, bih0, bhh0);
    lstm_layer_kernel<<<128, TPB, SMEM_BYTES>>>(Whh0, 0);
    gemm_xg_kernel<HH, true><<<gemm_grid, 256>>>(nullptr, Wih1, bih1, bhh1);
    lstm_layer_kernel<<<128, TPB, SMEM_BYTES>>>(Whh1, 1);
    epilogue_kernel<<<BB, 256>>>(W1, b1, W2, b2, out);
}

// round 14
// speedup vs baseline: 1.6586x; 1.6586x over previous
#include <cuda_runtime.h>
#include <cstdint>

#define BB   256
#define TT   512
#define II   64
#define HH   256
#define G4   1024   // 4*H
#define TPB  256
#define NGRP 16     // batch groups (16 rows each), 8 CTAs per group

// ---------------- global scratch (static; no allocations) ------------------
__device__ float g_xg[(size_t)BB * TT * G4];   // [t][b][unit*4+gate]  512MB
__device__ float g_h1[(size_t)BB * TT * HH];   // [b][t][h]            128MB
__device__ float g_h[2][BB * HH];              // [b][h] double-buffered
__device__ float g_last[BB * HH];
__device__ unsigned g_bar[NGRP * 32];          // per-group counters, 128B apart
__device__ unsigned g_rel[NGRP * 32];          // per-group release epochs

__global__ void init_sync_kernel() {
    int i = threadIdx.x;
    if (i < NGRP * 32) { g_bar[i] = 0u; g_rel[i] = 0u; }
}

// ---------------- helpers ---------------------------------------------------
__device__ __forceinline__ unsigned long long pack2(float x) {
    unsigned long long r;
    asm("mov.b64 %0, {%1, %1};" : "=l"(r) : "f"(x));
    return r;
}
__device__ __forceinline__ void fma2(unsigned long long& acc,
                                     unsigned long long a, unsigned long long b) {
    asm("fma.rn.f32x2 %0, %1, %2, %0;" : "+l"(acc) : "l"(a), "l"(b));
}
__device__ __forceinline__ float hadd2(unsigned long long v) {
    union { unsigned long long u; float2 f; } cv; cv.u = v;
    return cv.f.x + cv.f.y;
}
__device__ __forceinline__ float sigmoidf_(float x) {
    return 1.0f / (1.0f + __expf(-x));
}
__device__ __forceinline__ float tanhf_(float x) {
    return 1.0f - 2.0f / (__expf(2.0f * x) + 1.0f);
}

// Per-group barrier: 8 CTAs sharing a batch tile. Cheap: private cache line,
// 8 uncontended atomics + one release word.
__device__ __forceinline__ void group_barrier(int gidx, unsigned ep) {
    __syncthreads();
    if (threadIdx.x == 0) {
        __threadfence();   // publish h writes chip-wide (L2)
        unsigned a = atomicAdd(&g_bar[gidx], 1u) + 1u;
        if (a == ep * 8u) {
            atomicExch(&g_rel[gidx], ep);
        } else {
            while (*((volatile unsigned*)&g_rel[gidx]) < ep) {}
        }
        __threadfence();   // acquire
    }
    __syncthreads();
}

// ======================= bulk GEMM: xg = A @ W^T + bias =====================
// A[M=BB*TT][K] row-major (row m = b*T + t), W[G4][K] row-major with gate-block
// rows; output column ocol = unit*4 + gate, written to g_xg[t*BB + b][ocol].
template<int K, bool A_IS_H1>
__global__ void __launch_bounds__(256, 2)
gemm_xg_kernel(const float* __restrict__ Ain, const float* __restrict__ W,
               const float* __restrict__ bih, const float* __restrict__ bhh)
{
    __shared__ float As[16 * 132];
    __shared__ float Bs[16 * 132];
    const float* A = A_IS_H1 ? g_h1 : Ain;

    const int m0  = (int)(blockIdx.x >> 3) * 128;
    const int n0  = (int)(blockIdx.x & 7) * 128;
    const int tid = threadIdx.x;
    const int tx  = tid & 15;
    const int ty  = tid >> 4;
    const int lm  = tid >> 2;
    const int lk  = (tid & 3) * 4;

    unsigned long long acc[8][4];
    #pragma unroll
    for (int m = 0; m < 8; m++)
        #pragma unroll
        for (int n = 0; n < 4; n++) acc[m][n] = 0ull;

    for (int k0 = 0; k0 < K; k0 += 16) {
        #pragma unroll
        for (int i = 0; i < 2; i++) {
            int m = lm + i * 64;
            int ocol = n0 + m;
            int grow = (ocol & 3) * HH + (ocol >> 2);     // gate-interleave
            float4 va = *(const float4*)(A + (size_t)(m0 + m) * K + k0 + lk);
            float4 vb = *(const float4*)(W + (size_t)grow * K + k0 + lk);
            As[(lk + 0) * 132 + m] = va.x;  As[(lk + 1) * 132 + m] = va.y;
            As[(lk + 2) * 132 + m] = va.z;  As[(lk + 3) * 132 + m] = va.w;
            Bs[(lk + 0) * 132 + m] = vb.x;  Bs[(lk + 1) * 132 + m] = vb.y;
            Bs[(lk + 2) * 132 + m] = vb.z;  Bs[(lk + 3) * 132 + m] = vb.w;
        }
        __syncthreads();
        #pragma unroll
        for (int k = 0; k < 16; k++) {
            const float* ar = As + k * 132 + ty * 8;
            const float* br = Bs + k * 132 + tx * 8;
            ulonglong2 b0 = *(const ulonglong2*)(br);
            ulonglong2 b1 = *(const ulonglong2*)(br + 4);
            float4 a0 = *(const float4*)(ar);
            float4 a1 = *(const float4*)(ar + 4);
            float am[8] = {a0.x, a0.y, a0.z, a0.w, a1.x, a1.y, a1.z, a1.w};
            #pragma unroll
            for (int m = 0; m < 8; m++) {
                unsigned long long wd = pack2(am[m]);
                fma2(acc[m][0], wd, b0.x);
                fma2(acc[m][1], wd, b0.y);
                fma2(acc[m][2], wd, b1.x);
                fma2(acc[m][3], wd, b1.y);
            }
        }
        __syncthreads();
    }

    const int col = n0 + tx * 8;
    float bias[8];
    #pragma unroll
    for (int j = 0; j < 8; j++) {
        int oc = col + j;
        int grow = (oc & 3) * HH + (oc >> 2);
        bias[j] = bih[grow] + bhh[grow];
    }

    #pragma unroll
    for (int m = 0; m < 8; m++) {
        int mi   = m0 + ty * 8 + m;                  // = b*T + t
        int orow = (mi & (TT - 1)) * BB + (mi >> 9); // -> t*B + b
        float o[8];
        #pragma unroll
        for (int n = 0; n < 4; n++) {
            union { unsigned long long u; float2 f; } cv; cv.u = acc[m][n];
            o[2 * n]     = cv.f.x + bias[2 * n];
            o[2 * n + 1] = cv.f.y + bias[2 * n + 1];
        }
        float4* dst = (float4*)(g_xg + (size_t)orow * G4 + col);
        dst[0] = make_float4(o[0], o[1], o[2], o[3]);
        dst[1] = make_float4(o[4], o[5], o[6], o[7]);
    }
}

// ======================= group-synced recurrent layer =======================
// grid = 128 CTAs: 16 batch groups (16 rows) x 8 hidden tiles (32 units =
// 128 gate rows, gate-interleaved: row r -> unit r>>2, gate r&3).
// SMEM (floats):
//   Ws_t  [128][260]  weight rows, k-contiguous (k-pair packing for fp32x2)
//   Is_t  [16][260]   h_{t-1}, batch-row-major, k-contiguous
//   gts   [128][17]   gate pre-activations (Whh part)
//   h_s   [16][33]    h staging for coalesced writes
#define SM_WS  (128 * 260)
#define SM_IS  (16 * 260)
#define SM_GT  (128 * 17)
#define SM_HS  (16 * 33)
#define SMEM_FLOATS (SM_WS + SM_IS + SM_GT + SM_HS)
#define SMEM_BYTES  (SMEM_FLOATS * 4)

__global__ void __launch_bounds__(TPB, 1)
lstm_layer_kernel(const float* __restrict__ Whh, int layer)
{
    extern __shared__ float smem[];
    float* Ws_t = smem;
    float* Is_t = Ws_t + SM_WS;
    float* gts  = Is_t + SM_IS;
    float* h_s  = gts + SM_GT;

    const int tid  = threadIdx.x;
    const int bt   = blockIdx.x >> 3;   // 16 batch groups of 16
    const int ht   = blockIdx.x & 7;    // 8 hidden tiles of 32 units
    const int b0   = bt * 16;
    const int hu0u = ht * 32;
    const int gidx = bt * 32;           // barrier slot (128B-aligned line)

    // GEMM mapping: warp tile 16 rows x 16 batch; thread 2 rows x 4 batch
    const int warp = tid >> 5;
    const int lane = tid & 31;
    const int r0   = warp * 16 + (lane & 7) * 2;
    const int bq0  = (lane >> 3) * 4;

    // activation mapping: elements (uu=a_u0, bb) and (uu=a_u0+16, bb)
    const int a_bb = tid & 15;
    const int a_u0 = tid >> 4;          // 0..15

    // ---- load weight slice (rows gate-interleaved, k-contiguous) ----
    for (int i4 = tid; i4 < 128 * 64; i4 += TPB) {
        int r  = i4 >> 6;
        int kc = (i4 & 63) << 2;
        int grow = (r & 3) * HH + hu0u + (r >> 2);
        float4 v = *(const float4*)(Whh + (size_t)grow * HH + kc);
        *(float4*)(Ws_t + r * 260 + kc) = v;
    }
    // ---- zero our h slice in buffer 0 ----
    if (tid < 128) {
        int bb = tid >> 3, u4 = (tid & 7) * 4;
        *(float4*)(&g_h[0][(size_t)(b0 + bb) * HH + hu0u + u4]) =
            make_float4(0.f, 0.f, 0.f, 0.f);
    }

    float c0 = 0.0f, c1 = 0.0f;
    // prefetch xg for t=0 (independent of h)
    float4 xg0 = __ldcg((const float4*)(g_xg + (size_t)(b0 + a_bb) * G4
                                              + (hu0u + a_u0) * 4));
    float4 xg1 = __ldcg((const float4*)(g_xg + (size_t)(b0 + a_bb) * G4
                                              + (hu0u + a_u0 + 16) * 4));
    group_barrier(gidx, 1u);

    for (int t = 0; t < TT; t++) {
        const int cur = t & 1;
        const int nxt = cur ^ 1;

        // ---- fill Is_t[bb][k] from g_h[cur] (coalesced, L2-fresh) ----
        {
            const int fbb = tid >> 4;          // 0..15 batch row
            const int fcj = tid & 15;          // chunk lane
            const float* src = g_h[cur] + (size_t)(b0 + fbb) * HH;
            float* dstrow = Is_t + fbb * 260;
            #pragma unroll
            for (int j = 0; j < 4; j++) {
                int c = fcj + 16 * j;          // float4 chunk 0..63
                float4 v = __ldcg((const float4*)(src + c * 4));
                *(float4*)(dstrow + c * 4) = v;
            }
        }
        __syncthreads();

        // ---- GEMM: gts[r][b] = sum_k Whh_r[k] * h[b][k]  (k-pair fp32x2) ----
        {
            unsigned long long acc[2][4];
            #pragma unroll
            for (int r = 0; r < 2; r++)
                #pragma unroll
                for (int j = 0; j < 4; j++) acc[r][j] = 0ull;

            const float* wp0 = Ws_t + r0 * 260;
            const float* wp1 = wp0 + 260;
            const float* ip  = Is_t + bq0 * 260;

            #pragma unroll 4
            for (int kc = 0; kc < HH; kc += 4) {
                ulonglong2 w0 = *(const ulonglong2*)(wp0 + kc);
                ulonglong2 w1 = *(const ulonglong2*)(wp1 + kc);
                ulonglong2 h0 = *(const ulonglong2*)(ip + 0 * 260 + kc);
                ulonglong2 h1 = *(const ulonglong2*)(ip + 1 * 260 + kc);
                ulonglong2 h2 = *(const ulonglong2*)(ip + 2 * 260 + kc);
                ulonglong2 h3 = *(const ulonglong2*)(ip + 3 * 260 + kc);
                fma2(acc[0][0], w0.x, h0.x);  fma2(acc[0][0], w0.y, h0.y);
                fma2(acc[0][1], w0.x, h1.x);  fma2(acc[0][1], w0.y, h1.y);
                fma2(acc[0][2], w0.x, h2.x);  fma2(acc[0][2], w0.y, h2.y);
                fma2(acc[0][3], w0.x, h3.x);  fma2(acc[0][3], w0.y, h3.y);
                fma2(acc[1][0], w1.x, h0.x);  fma2(acc[1][0], w1.y, h0.y);
                fma2(acc[1][1], w1.x, h1.x);  fma2(acc[1][1], w1.y, h1.y);
                fma2(acc[1][2], w1.x, h2.x);  fma2(acc[1][2], w1.y, h2.y);
                fma2(acc[1][3], w1.x, h3.x);  fma2(acc[1][3], w1.y, h3.y);
            }
            #pragma unroll
            for (int r = 0; r < 2; r++)
                #pragma unroll
                for (int j = 0; j < 4; j++)
                    gts[(r0 + r) * 17 + bq0 + j] = hadd2(acc[r][j]);
        }
        __syncthreads();

        // ---- activation: 2 elements per thread, c in registers ----
        {
            float gi = gts[(a_u0 * 4 + 0) * 17 + a_bb] + xg0.x;
            float gf = gts[(a_u0 * 4 + 1) * 17 + a_bb] + xg0.y;
            float gg = gts[(a_u0 * 4 + 2) * 17 + a_bb] + xg0.z;
            float go = gts[(a_u0 * 4 + 3) * 17 + a_bb] + xg0.w;
            c0 = sigmoidf_(gf) * c0 + sigmoidf_(gi) * tanhf_(gg);
            float h0v = sigmoidf_(go) * tanhf_(c0);
            h_s[a_bb * 33 + a_u0] = h0v;

            int u1 = a_u0 + 16;
            gi = gts[(u1 * 4 + 0) * 17 + a_bb] + xg1.x;
            gf = gts[(u1 * 4 + 1) * 17 + a_bb] + xg1.y;
            gg = gts[(u1 * 4 + 2) * 17 + a_bb] + xg1.z;
            go = gts[(u1 * 4 + 3) * 17 + a_bb] + xg1.w;
            c1 = sigmoidf_(gf) * c1 + sigmoidf_(gi) * tanhf_(gg);
            float h1v = sigmoidf_(go) * tanhf_(c1);
            h_s[a_bb * 33 + u1] = h1v;
        }
        __syncthreads();

        // ---- write h to g_h[nxt] (+ h1 / last), coalesced via h_s ----
        if (tid < 128) {
            int bb = tid >> 3, u4 = (tid & 7) * 4;
            float4 v = make_float4(h_s[bb * 33 + u4 + 0], h_s[bb * 33 + u4 + 1],
                                   h_s[bb * 33 + u4 + 2], h_s[bb * 33 + u4 + 3]);
            *(float4*)(&g_h[nxt][(size_t)(b0 + bb) * HH + hu0u + u4]) = v;
        } else {
            int t2 = tid - 128;
            int bb = t2 >> 3, u4 = (t2 & 7) * 4;
            float4 v = make_float4(h_s[bb * 33 + u4 + 0], h_s[bb * 33 + u4 + 1],
                                   h_s[bb * 33 + u4 + 2], h_s[bb * 33 + u4 + 3]);
            if (layer == 0) {
                *(float4*)(&g_h1[((size_t)(b0 + bb) * TT + t) * HH + hu0u + u4]) = v;
            } else if (t == TT - 1) {
                *(float4*)(&g_last[(size_t)(b0 + bb) * HH + hu0u + u4]) = v;
            }
        }

        // prefetch xg for t+1; its latency hides in the barrier wait
        if (t + 1 < TT) {
            xg0 = __ldcg((const float4*)(g_xg + (size_t)((t + 1) * BB + b0 + a_bb) * G4
                                               + (hu0u + a_u0) * 4));
            xg1 = __ldcg((const float4*)(g_xg + (size_t)((t + 1) * BB + b0 + a_bb) * G4
                                               + (hu0u + a_u0 + 16) * 4));
        }
        group_barrier(gidx, (unsigned)(t + 2));
    }
}

// ======================= epilogue ===========================================
__global__ void __launch_bounds__(256)
epilogue_kernel(const float* __restrict__ W1, const float* __restrict__ b1,
                const float* __restrict__ W2, const float* __restrict__ b2,
                float* __restrict__ out)
{
    const int b    = blockIdx.x;
    const int tid  = threadIdx.x;
    const int lane = tid & 31;
    const int warp = tid >> 5;

    __shared__ float last_s[HH];
    __shared__ float y_s[5 * HH];

    last_s[tid] = g_last[(size_t)b * HH + tid];
    __syncthreads();

    for (int j = warp; j < 5 * HH; j += 8) {
        const float* wr = W1 + (size_t)j * HH;
        float acc = 0.0f;
        for (int k = lane; k < HH; k += 32) acc += wr[k] * last_s[k];
        #pragma unroll
        for (int o = 16; o; o >>= 1) acc += __shfl_down_sync(0xffffffffu, acc, o);
        if (lane == 0) y_s[j] = acc + b1[j];
    }
    __syncthreads();

    if (warp < 4) {
        const float* wr = W2 + (size_t)warp * (5 * HH);
        float acc = 0.0f;
        for (int j = lane; j < 5 * HH; j += 32) acc += wr[j] * y_s[j];
        #pragma unroll
        for (int o = 16; o; o >>= 1) acc += __shfl_down_sync(0xffffffffu, acc, o);
        if (lane == 0) out[b * 4 + warp] = acc + b2[warp];
    }
}

// ======================= launcher ===========================================
extern "C" void kernel_launch(void* const* d_in, const int* in_sizes, int n_in,
                              void* d_out, int out_size)
{
    const float* x    = (const float*)d_in[0];
    const float* Wih0 = (const float*)d_in[1];
    const float* Whh0 = (const float*)d_in[2];
    const float* bih0 = (const float*)d_in[3];
    const float* bhh0 = (const float*)d_in[4];
    const float* Wih1 = (const float*)d_in[5];
    const float* Whh1 = (const float*)d_in[6];
    const float* bih1 = (const float*)d_in[7];
    const float* bhh1 = (const float*)d_in[8];
    const float* W1   = (const float*)d_in[9];
    const float* b1   = (const float*)d_in[10];
    const float* W2   = (const float*)d_in[11];
    const float* b2   = (const float*)d_in[12];
    float* out = (float*)d_out;

    cudaFuncSetAttribute(lstm_layer_kernel,
                         cudaFuncAttributeMaxDynamicSharedMemorySize, SMEM_BYTES);

    const int gemm_grid = (BB * TT / 128) * 8;   // 8192

    gemm_xg_kernel<II, false><<<gemm_grid, 256>>>(x, Wih0, bih0, bhh0);
    init_sync_kernel<<<1, NGRP * 32>>>();
    lstm_layer_kernel<<<128, TPB, SMEM_BYTES>>>(Whh0, 0);
    gemm_xg_kernel<HH, true><<<gemm_grid, 256>>>(nullptr, Wih1, bih1, bhh1);
    init_sync_kernel<<<1, NGRP * 32>>>();
    lstm_layer_kernel<<<128, TPB, SMEM_BYTES>>>(Whh1, 1);
    epilogue_kernel<<<BB, 256>>>(W1, b1, W2, b2, out);
}

// round 16
// speedup vs baseline: 2.2119x; 1.3336x over previous
#include <cuda_runtime.h>
#include <cstdint>

#define BB   256
#define TT   512
#define II   64
#define HH   256
#define G4   1024   // 4*H
#define TPB  256
#define NGRP 16     // batch groups (16 rows each), 16 CTAs per group

// ---------------- global scratch (static; no allocations) ------------------
__device__ float g_xg[(size_t)BB * TT * G4];   // [t][b][unit*4+gate]  512MB
__device__ float g_h1[(size_t)BB * TT * HH];   // [b][t][h]            128MB
__device__ float g_h[2][BB * HH];              // [b][h] double-buffered
__device__ float g_last[BB * HH];
__device__ unsigned g_bar[NGRP * 32];          // per-group counters, 128B apart
__device__ unsigned g_rel[NGRP * 32];          // per-group release epochs

__global__ void init_sync_kernel() {
    int i = threadIdx.x;
    if (i < NGRP * 32) { g_bar[i] = 0u; g_rel[i] = 0u; }
}

// ---------------- helpers ---------------------------------------------------
__device__ __forceinline__ unsigned long long pack2(float x) {
    unsigned long long r;
    asm("mov.b64 %0, {%1, %1};" : "=l"(r) : "f"(x));
    return r;
}
__device__ __forceinline__ unsigned long long packxy(float x, float y) {
    unsigned long long r;
    asm("mov.b64 %0, {%1, %2};" : "=l"(r) : "f"(x), "f"(y));
    return r;
}
__device__ __forceinline__ void fma2(unsigned long long& acc,
                                     unsigned long long a, unsigned long long b) {
    asm("fma.rn.f32x2 %0, %1, %2, %0;" : "+l"(acc) : "l"(a), "l"(b));
}
__device__ __forceinline__ float hadd2(unsigned long long v) {
    union { unsigned long long u; float2 f; } cv; cv.u = v;
    return cv.f.x + cv.f.y;
}
__device__ __forceinline__ float sigmoidf_(float x) {
    return 1.0f / (1.0f + __expf(-x));
}
__device__ __forceinline__ float tanhf_(float x) {
    return 1.0f - 2.0f / (__expf(2.0f * x) + 1.0f);
}

// Per-group barrier: 16 CTAs sharing a batch tile; private cache line.
__device__ __forceinline__ void group_barrier(int gidx, unsigned ep) {
    __syncthreads();
    if (threadIdx.x == 0) {
        __threadfence();   // publish h writes chip-wide (L2)
        unsigned a = atomicAdd(&g_bar[gidx], 1u) + 1u;
        if (a == ep * 16u) {
            atomicExch(&g_rel[gidx], ep);
        } else {
            while (*((volatile unsigned*)&g_rel[gidx]) < ep) {}
        }
        __threadfence();   // acquire
    }
    __syncthreads();
}

// ======================= bulk GEMM: xg = A @ W^T + bias =====================
// A[M=BB*TT][K] row-major (row m = b*T + t), W[G4][K] row-major with gate-block
// rows; output column ocol = unit*4 + gate, written to g_xg[t*BB + b][ocol].
template<int K, bool A_IS_H1>
__global__ void __launch_bounds__(256, 2)
gemm_xg_kernel(const float* __restrict__ Ain, const float* __restrict__ W,
               const float* __restrict__ bih, const float* __restrict__ bhh)
{
    __shared__ float As[16 * 132];
    __shared__ float Bs[16 * 132];
    const float* A = A_IS_H1 ? g_h1 : Ain;

    const int m0  = (int)(blockIdx.x >> 3) * 128;
    const int n0  = (int)(blockIdx.x & 7) * 128;
    const int tid = threadIdx.x;
    const int tx  = tid & 15;
    const int ty  = tid >> 4;
    const int lm  = tid >> 2;
    const int lk  = (tid & 3) * 4;

    unsigned long long acc[8][4];
    #pragma unroll
    for (int m = 0; m < 8; m++)
        #pragma unroll
        for (int n = 0; n < 4; n++) acc[m][n] = 0ull;

    for (int k0 = 0; k0 < K; k0 += 16) {
        #pragma unroll
        for (int i = 0; i < 2; i++) {
            int m = lm + i * 64;
            int ocol = n0 + m;
            int grow = (ocol & 3) * HH + (ocol >> 2);     // gate-interleave
            float4 va = *(const float4*)(A + (size_t)(m0 + m) * K + k0 + lk);
            float4 vb = *(const float4*)(W + (size_t)grow * K + k0 + lk);
            As[(lk + 0) * 132 + m] = va.x;  As[(lk + 1) * 132 + m] = va.y;
            As[(lk + 2) * 132 + m] = va.z;  As[(lk + 3) * 132 + m] = va.w;
            Bs[(lk + 0) * 132 + m] = vb.x;  Bs[(lk + 1) * 132 + m] = vb.y;
            Bs[(lk + 2) * 132 + m] = vb.z;  Bs[(lk + 3) * 132 + m] = vb.w;
        }
        __syncthreads();
        #pragma unroll
        for (int k = 0; k < 16; k++) {
            const float* ar = As + k * 132 + ty * 8;
            const float* br = Bs + k * 132 + tx * 8;
            ulonglong2 b0 = *(const ulonglong2*)(br);
            ulonglong2 b1 = *(const ulonglong2*)(br + 4);
            float4 a0 = *(const float4*)(ar);
            float4 a1 = *(const float4*)(ar + 4);
            float am[8] = {a0.x, a0.y, a0.z, a0.w, a1.x, a1.y, a1.z, a1.w};
            #pragma unroll
            for (int m = 0; m < 8; m++) {
                unsigned long long wd = pack2(am[m]);
                fma2(acc[m][0], wd, b0.x);
                fma2(acc[m][1], wd, b0.y);
                fma2(acc[m][2], wd, b1.x);
                fma2(acc[m][3], wd, b1.y);
            }
        }
        __syncthreads();
    }

    const int col = n0 + tx * 8;
    float bias[8];
    #pragma unroll
    for (int j = 0; j < 8; j++) {
        int oc = col + j;
        int grow = (oc & 3) * HH + (oc >> 2);
        bias[j] = bih[grow] + bhh[grow];
    }

    #pragma unroll
    for (int m = 0; m < 8; m++) {
        int mi   = m0 + ty * 8 + m;                  // = b*T + t
        int orow = (mi & (TT - 1)) * BB + (mi >> 9); // -> t*B + b
        float o[8];
        #pragma unroll
        for (int n = 0; n < 4; n++) {
            union { unsigned long long u; float2 f; } cv; cv.u = acc[m][n];
            o[2 * n]     = cv.f.x + bias[2 * n];
            o[2 * n + 1] = cv.f.y + bias[2 * n + 1];
        }
        float4* dst = (float4*)(g_xg + (size_t)orow * G4 + col);
        dst[0] = make_float4(o[0], o[1], o[2], o[3]);
        dst[1] = make_float4(o[4], o[5], o[6], o[7]);
    }
}

// ================ recurrent layer: weights-in-registers =====================
// grid = 256 CTAs = 16 batch groups (16 rows) x 16 unit tiles (16 units =
// 64 gate rows, gate-interleaved: row r -> unit r>>2, gate r&3).
// 2 CTAs/SM; thread = (row r = tid&63, k-slice ks = tid>>6), holds its 64
// Whh values in 32 packed f32x2 registers for the whole layer.
// SMEM: Is[16][260] h_{t-1}; part[64][65] split-k partials (stride 65 ->
// conflict-free column writes).
__global__ void __launch_bounds__(TPB, 2)
lstm_layer_kernel(const float* __restrict__ Whh, int layer)
{
    __shared__ float Is[16 * 260];
    __shared__ float part[64 * 65];

    const int tid  = threadIdx.x;
    const int bt   = blockIdx.x >> 4;   // 16 batch groups
    const int ht   = blockIdx.x & 15;   // 16 unit tiles
    const int b0   = bt * 16;
    const int hu0  = ht * 16;
    const int gidx = bt * 32;           // barrier slot (128B line per group)

    const int r  = tid & 63;            // gate row within tile
    const int ks = tid >> 6;            // k-slice (64 k's)

    // activation mapping: one (unit, batch) cell per thread
    const int a_uu = tid & 15;
    const int a_b  = tid >> 4;

    // ---- load this thread's 64 weights into registers (packed pairs) ----
    unsigned long long w2[32];
    {
        const int grow = (r & 3) * HH + hu0 + (r >> 2);
        const float* wp = Whh + (size_t)grow * HH + ks * 64;
        #pragma unroll
        for (int i = 0; i < 16; i++) {
            float4 v = *(const float4*)(wp + i * 4);
            w2[2 * i]     = packxy(v.x, v.y);
            w2[2 * i + 1] = packxy(v.z, v.w);
        }
    }

    // ---- zero our h slice in buffer 0 ----
    g_h[0][(size_t)(b0 + a_b) * HH + hu0 + a_uu] = 0.0f;

    float c = 0.0f;
    // prefetch xg for t=0
    float4 xgv = __ldcg((const float4*)(g_xg + (size_t)(b0 + a_b) * G4
                                              + (hu0 + a_uu) * 4));
    group_barrier(gidx, 1u);

    for (int t = 0; t < TT; t++) {
        const int cur = t & 1;
        const int nxt = cur ^ 1;

        // ---- fill Is[b][k] from g_h[cur] (coalesced, L2-fresh) ----
        {
            const int fbb = tid >> 4;          // batch row 0..15
            const int fcj = tid & 15;          // chunk lane
            const float* src = g_h[cur] + (size_t)(b0 + fbb) * HH;
            float* dstrow = Is + fbb * 260;
            #pragma unroll
            for (int j = 0; j < 4; j++) {
                int cch = fcj + 16 * j;        // float4 chunk 0..63
                float4 v = __ldcg((const float4*)(src + cch * 4));
                *(float4*)(dstrow + cch * 4) = v;
            }
        }
        __syncthreads();

        // ---- GEMM: part[r][b*4+ks] = sum over this k-slice of W.h ----
        {
            const float* hb = Is + ks * 64;    // + b*260
            #pragma unroll 2
            for (int b = 0; b < 16; b += 2) {
                unsigned long long acc0 = 0ull, acc1 = 0ull;
                const float* h0p = hb + b * 260;
                const float* h1p = h0p + 260;
                #pragma unroll
                for (int kk = 0; kk < 64; kk += 4) {
                    ulonglong2 ha = *(const ulonglong2*)(h0p + kk);
                    ulonglong2 hc = *(const ulonglong2*)(h1p + kk);
                    fma2(acc0, w2[kk / 2],     ha.x);
                    fma2(acc0, w2[kk / 2 + 1], ha.y);
                    fma2(acc1, w2[kk / 2],     hc.x);
                    fma2(acc1, w2[kk / 2 + 1], hc.y);
                }
                part[r * 65 + b * 4 + ks]       = hadd2(acc0);
                part[r * 65 + (b + 1) * 4 + ks] = hadd2(acc1);
            }
        }
        __syncthreads();

        // ---- activation: reduce 4 slices x 4 gates, update c, write h ----
        {
            const float* pr = part + (a_uu * 4) * 65 + a_b * 4;
            float gi = pr[0*65+0] + pr[0*65+1] + pr[0*65+2] + pr[0*65+3] + xgv.x;
            float gf = pr[1*65+0] + pr[1*65+1] + pr[1*65+2] + pr[1*65+3] + xgv.y;
            float gg = pr[2*65+0] + pr[2*65+1] + pr[2*65+2] + pr[2*65+3] + xgv.z;
            float go = pr[3*65+0] + pr[3*65+1] + pr[3*65+2] + pr[3*65+3] + xgv.w;
            c = sigmoidf_(gf) * c + sigmoidf_(gi) * tanhf_(gg);
            float h = sigmoidf_(go) * tanhf_(c);

            g_h[nxt][(size_t)(b0 + a_b) * HH + hu0 + a_uu] = h;
            if (layer == 0) {
                g_h1[((size_t)(b0 + a_b) * TT + t) * HH + hu0 + a_uu] = h;
            } else if (t == TT - 1) {
                g_last[(size_t)(b0 + a_b) * HH + hu0 + a_uu] = h;
            }
        }

        // prefetch xg for t+1; latency hides in the barrier wait
        if (t + 1 < TT) {
            xgv = __ldcg((const float4*)(g_xg + (size_t)((t + 1) * BB + b0 + a_b) * G4
                                               + (hu0 + a_uu) * 4));
        }
        group_barrier(gidx, (unsigned)(t + 2));
    }
}

// ======================= epilogue ===========================================
__global__ void __launch_bounds__(256)
epilogue_kernel(const float* __restrict__ W1, const float* __restrict__ b1,
                const float* __restrict__ W2, const float* __restrict__ b2,
                float* __restrict__ out)
{
    const int b    = blockIdx.x;
    const int tid  = threadIdx.x;
    const int lane = tid & 31;
    const int warp = tid >> 5;

    __shared__ float last_s[HH];
    __shared__ float y_s[5 * HH];

    last_s[tid] = g_last[(size_t)b * HH + tid];
    __syncthreads();

    for (int j = warp; j < 5 * HH; j += 8) {
        const float* wr = W1 + (size_t)j * HH;
        float acc = 0.0f;
        for (int k = lane; k < HH; k += 32) acc += wr[k] * last_s[k];
        #pragma unroll
        for (int o = 16; o; o >>= 1) acc += __shfl_down_sync(0xffffffffu, acc, o);
        if (lane == 0) y_s[j] = acc + b1[j];
    }
    __syncthreads();

    if (warp < 4) {
        const float* wr = W2 + (size_t)warp * (5 * HH);
        float acc = 0.0f;
        for (int j = lane; j < 5 * HH; j += 32) acc += wr[j] * y_s[j];
        #pragma unroll
        for (int o = 16; o; o >>= 1) acc += __shfl_down_sync(0xffffffffu, acc, o);
        if (lane == 0) out[b * 4 + warp] = acc + b2[warp];
    }
}

// ======================= launcher ===========================================
extern "C" void kernel_launch(void* const* d_in, const int* in_sizes, int n_in,
                              void* d_out, int out_size)
{
    const float* x    = (const float*)d_in[0];
    const float* Wih0 = (const float*)d_in[1];
    const float* Whh0 = (const float*)d_in[2];
    const float* bih0 = (const float*)d_in[3];
    const float* bhh0 = (const float*)d_in[4];
    const float* Wih1 = (const float*)d_in[5];
    const float* Whh1 = (const float*)d_in[6];
    const float* bih1 = (const float*)d_in[7];
    const float* bhh1 = (const float*)d_in[8];
    const float* W1   = (const float*)d_in[9];
    const float* b1   = (const float*)d_in[10];
    const float* W2   = (const float*)d_in[11];
    const float* b2   = (const float*)d_in[12];
    float* out = (float*)d_out;

    const int gemm_grid = (BB * TT / 128) * 8;   // 8192

    gemm_xg_kernel<II, false><<<gemm_grid, 256>>>(x, Wih0, bih0, bhh0);
    init_sync_kernel<<<1, NGRP * 32>>>();
    lstm_layer_kernel<<<256, TPB>>>(Whh0, 0);
    gemm_xg_kernel<HH, true><<<gemm_grid, 256>>>(nullptr, Wih1, bih1, bhh1);
    init_sync_kernel<<<1, NGRP * 32>>>();
    lstm_layer_kernel<<<256, TPB>>>(Whh1, 1);
    epilogue_kernel<<<BB, 256>>>(W1, b1, W2, b2, out);
}